// round 6
// baseline (speedup 1.0000x reference)
#include <cuda_runtime.h>
#include <cstdint>

// ---------------------------------------------------------------------------
// FP4 block quant-dequant, BLOCK=64, scale = 95th pct of |x| per block,
// double-quantized scales (global min/max over blocks).
//
// TWO launches only:
//   k_pass1 : TMA bulk load -> smem -> regs; top-5 + premultiplied-threshold
//             quantize; per-CTA partial min/max + last-CTA global reduction
//             (self-resetting counter -> no init kernel)
//   k_pass2 : arithmetic decode, per-CTA ds (32 blocks) in smem,
//             2 float4/thread, streaming stores
// ---------------------------------------------------------------------------

#define NBLK_CAP 262144   // 16777216 / 64
#define P1_THREADS 128
#define BLK_PER_CTA 128   // one 64-elt block per thread
#define MAX_GRID1 (NBLK_CAP / BLK_PER_CTA)   // 2048

__device__ float    g_scales[NBLK_CAP];
__device__ unsigned g_codes32[NBLK_CAP * 8];  // 8 u32 per block, element order
__device__ float    g_part_min[MAX_GRID1];
__device__ float    g_part_max[MAX_GRID1];
__device__ unsigned g_ctr = 0;                // self-resetting
__device__ float4   g_params;                 // {smin, ss, iss, cond}

// ---- minimal mbarrier / bulk-copy PTX helpers ----
__device__ __forceinline__ unsigned smem_u32(const void* p) {
    return (unsigned)__cvta_generic_to_shared(p);
}
__device__ __forceinline__ void mbar_init(unsigned a, unsigned cnt) {
    asm volatile("mbarrier.init.shared.b64 [%0], %1;" :: "r"(a), "r"(cnt) : "memory");
}
__device__ __forceinline__ void mbar_expect_tx(unsigned a, unsigned bytes) {
    asm volatile("mbarrier.arrive.expect_tx.shared.b64 _, [%0], %1;"
                 :: "r"(a), "r"(bytes) : "memory");
}
__device__ __forceinline__ void bulk_g2s(unsigned dst, const void* src,
                                         unsigned bytes, unsigned mbar) {
    asm volatile(
        "cp.async.bulk.shared::cta.global.mbarrier::complete_tx::bytes "
        "[%0], [%1], %2, [%3];"
        :: "r"(dst), "l"(src), "r"(bytes), "r"(mbar) : "memory");
}
__device__ __forceinline__ void mbar_wait(unsigned a, unsigned phase) {
    asm volatile(
        "{\n\t"
        ".reg .pred P;\n\t"
        "WL%=:\n\t"
        "mbarrier.try_wait.parity.acquire.cta.shared::cta.b64 P, [%0], %1;\n\t"
        "@!P bra WL%=;\n\t"
        "}"
        :: "r"(a), "r"(phase) : "memory");
}

// Branchless insert of v (>=0) into descending top-5 (t0 >= ... >= t4).
__device__ __forceinline__ void ins5(float& t0, float& t1, float& t2,
                                     float& t3, float& t4, float v) {
    float a;
    a = fminf(t0, v); t0 = fmaxf(t0, v);
    float b = fminf(t1, a); t1 = fmaxf(t1, a);
    a = fminf(t2, b); t2 = fmaxf(t2, b);
    b = fminf(t3, a); t3 = fmaxf(t3, a);
    t4 = fmaxf(t4, b);
}

// Quantize vs per-block premultiplied midpoints C[5] (uint bits of
// s*{0.375,0.875,1.25,1.75,2.5}); uint compare == float compare for
// positives. Code: bit3 = sign, bits[2:0] = level 0..5.
__device__ __forceinline__ unsigned quant1(float xx, const unsigned* C) {
    unsigned bits = __float_as_uint(xx);
    unsigned mag  = bits & 0x7FFFFFFFu;
    unsigned k = (unsigned)(mag > C[0]) + (unsigned)(mag > C[1])
               + (unsigned)(mag > C[2]) + (unsigned)(mag > C[3])
               + (unsigned)(mag > C[4]);
    return k + ((bits >> 28) & 8u);
}

__global__ void __launch_bounds__(P1_THREADS) k_pass1(const float* __restrict__ x,
                                                      int nblocks, int n) {
    __shared__ __align__(16) float4 sm[BLK_PER_CTA * 16];  // 32 KB
    __shared__ __align__(8) unsigned long long mbar;
    __shared__ float shm[4], shx[4];
    __shared__ bool amLast;

    int tid = threadIdx.x;
    long cta_blk0 = (long)blockIdx.x * BLK_PER_CTA;
    long e_base = cta_blk0 * 64;
    bool full = e_base + BLK_PER_CTA * 64 <= (long)n;

    if (full) {
        if (tid == 0) mbar_init(smem_u32(&mbar), 1);
        __syncthreads();
        if (tid == 0) {
            unsigned mb = smem_u32(&mbar);
            mbar_expect_tx(mb, BLK_PER_CTA * 256);
            bulk_g2s(smem_u32(sm), x + e_base, BLK_PER_CTA * 256, mb);
        }
        mbar_wait(smem_u32(&mbar), 0);
    } else {
        #pragma unroll
        for (int k = 0; k < 16; k++) {
            int l4 = tid + k * P1_THREADS;
            long e = e_base + (long)l4 * 4;
            float4 v;
            v.x = (e + 0 < (long)n) ? x[e + 0] : 0.0f;
            v.y = (e + 1 < (long)n) ? x[e + 1] : 0.0f;
            v.z = (e + 2 < (long)n) ? x[e + 2] : 0.0f;
            v.w = (e + 3 < (long)n) ? x[e + 3] : 0.0f;
            sm[l4] = v;
        }
        __syncthreads();
    }

    long b = cta_blk0 + tid;
    bool valid = b < (long)nblocks;
    float vmn = __uint_as_float(0x7F800000u);
    float vmx = 0.0f;

    if (valid) {
        // single smem read, rotated (conflict-free), register-resident
        float4 vals[16];
        #pragma unroll
        for (int i = 0; i < 16; i++)
            vals[i] = sm[(tid << 4) | ((i + tid) & 15)];

        // ---- top-5 of |x| ----
        float t0 = 0.f, t1 = 0.f, t2 = 0.f, t3 = 0.f, t4 = 0.f;
        #pragma unroll
        for (int i = 0; i < 16; i++) {
            ins5(t0, t1, t2, t3, t4, fabsf(vals[i].x));
            ins5(t0, t1, t2, t3, t4, fabsf(vals[i].y));
            ins5(t0, t1, t2, t3, t4, fabsf(vals[i].z));
            ins5(t0, t1, t2, t3, t4, fabsf(vals[i].w));
        }

        // 95th pct linear interp: idx = 0.95*63 between sorted[59]=t4,
        // sorted[60]=t3.
        const float idxf = 0.95f * 63.0f;
        const float hw   = idxf - 59.0f;
        const float lw   = 1.0f - hw;
        float s = t4 * lw + t3 * hw;
        s = fmaxf(s, 1e-8f);
        g_scales[b] = s;
        vmn = s; vmx = s;

        unsigned C[5];
        C[0] = __float_as_uint(s * 0.375f);
        C[1] = __float_as_uint(s * 0.875f);
        C[2] = __float_as_uint(s * 1.25f);
        C[3] = __float_as_uint(s * 1.75f);
        C[4] = __float_as_uint(s * 2.5f);

        // ---- quantize + pack (undo rotation when placing nibbles) ----
        unsigned w[8];
        #pragma unroll
        for (int i = 0; i < 8; i++) w[i] = 0u;
        #pragma unroll
        for (int i = 0; i < 16; i++) {
            int j = (i + tid) & 15;   // true float4 position in block
            unsigned nib =  quant1(vals[i].x, C)
                         + (quant1(vals[i].y, C) << 4)
                         + (quant1(vals[i].z, C) << 8)
                         + (quant1(vals[i].w, C) << 12);
            w[j >> 1] += nib << ((j & 1) * 16);
        }
        uint4* c4 = reinterpret_cast<uint4*>(g_codes32);
        c4[(size_t)b * 2 + 0] = make_uint4(w[0], w[1], w[2], w[3]);
        c4[(size_t)b * 2 + 1] = make_uint4(w[4], w[5], w[6], w[7]);
    }

    // ---- CTA min/max reduce -> per-CTA partial (plain store) ----
    #pragma unroll
    for (int o = 16; o > 0; o >>= 1) {
        vmn = fminf(vmn, __shfl_xor_sync(0xFFFFFFFFu, vmn, o));
        vmx = fmaxf(vmx, __shfl_xor_sync(0xFFFFFFFFu, vmx, o));
    }
    int wid = tid >> 5;
    if ((tid & 31) == 0) { shm[wid] = vmn; shx[wid] = vmx; }
    __syncthreads();
    if (tid == 0) {
        float mn = shm[0], mx = shx[0];
        #pragma unroll
        for (int i = 1; i < 4; i++) {
            mn = fminf(mn, shm[i]);
            mx = fmaxf(mx, shx[i]);
        }
        g_part_min[blockIdx.x] = mn;
        g_part_max[blockIdx.x] = mx;
        __threadfence();
        unsigned v = atomicAdd(&g_ctr, 1u);
        amLast = (v == gridDim.x - 1);
    }
    __syncthreads();

    // ---- last CTA: reduce partials, publish params, reset counter ----
    if (amLast) {
        float mn = __uint_as_float(0x7F800000u);
        float mx = 0.0f;
        for (int i = tid; i < (int)gridDim.x; i += P1_THREADS) {
            mn = fminf(mn, g_part_min[i]);
            mx = fmaxf(mx, g_part_max[i]);
        }
        #pragma unroll
        for (int o = 16; o > 0; o >>= 1) {
            mn = fminf(mn, __shfl_xor_sync(0xFFFFFFFFu, mn, o));
            mx = fmaxf(mx, __shfl_xor_sync(0xFFFFFFFFu, mx, o));
        }
        if ((tid & 31) == 0) { shm[wid] = mn; shx[wid] = mx; }
        __syncthreads();
        if (tid == 0) {
            float smin = shm[0], smax = shx[0];
            #pragma unroll
            for (int i = 1; i < 4; i++) {
                smin = fminf(smin, shm[i]);
                smax = fmaxf(smax, shx[i]);
            }
            bool cond = smax > smin;
            float ss  = cond ? (smax - smin) / 255.0f : 1.0f;
            g_params = make_float4(smin, ss, 1.0f / ss, cond ? 1.0f : 0.0f);
            g_ctr = 0;           // self-reset for next graph replay
            __threadfence();
        }
    }
}

// Decode 4-bit code: magnitudes {0,0.75,1,1.5,2,3} linear in fp32 bits:
// eb = 0x3F000000 + (k<<22) for k>0; bit3 -> sign.
__device__ __forceinline__ float dec1(unsigned c, float ds) {
    unsigned k  = c & 7u;
    unsigned eb = 0x3F000000u + (k << 22);
    eb = k ? eb : 0u;
    eb |= (c & 8u) << 28;
    return __uint_as_float(eb) * ds;
}

__device__ __forceinline__ float4 dec4(unsigned nib, float ds) {
    float4 o;
    o.x = dec1( nib        & 15u, ds);
    o.y = dec1((nib >>  4) & 15u, ds);
    o.z = dec1((nib >>  8) & 15u, ds);
    o.w = dec1((nib >> 12) & 15u, ds);
    return o;
}

// One CTA covers 512 float4s = 32 quant blocks; ds per block in smem.
__global__ void __launch_bounds__(256) k_pass2(float* __restrict__ out,
                                               int nblocks, int n) {
    __shared__ float sds[32];
    int tid = threadIdx.x;

    // ds = round((s-smin)/ss)*ss, ss = (smax-smin)/255 (smin dropped in
    // dequant — faithful to reference)
    if (tid < 32) {
        int b = blockIdx.x * 32 + tid;
        float dsv = 0.0f;
        if (b < nblocks) {
            float4 P = g_params;      // {smin, ss, iss, cond}
            float s  = g_scales[b];
            float d  = s - P.x;
            float q0 = d * P.z;
            float q  = fmaf(fmaf(-P.y, q0, d), P.z, q0);  // == fl(d/ss)
            q = rintf(q);                                 // half-to-even
            q = fminf(fmaxf(q, 0.0f), 255.0f);
            if (P.w == 0.0f) q = 0.0f;
            dsv = q * P.y;
        }
        sds[tid] = dsv;
    }
    __syncthreads();

    int n4 = (n + 3) >> 2;
    int f0 = blockIdx.x * 512 + tid;
    int f1 = f0 + 256;
    bool v0 = f0 < n4, v1 = f1 < n4;

    unsigned cw0 = 0, cw1 = 0;
    if (v0) cw0 = g_codes32[f0 >> 1];
    if (v1) cw1 = g_codes32[f1 >> 1];

    float ds0 = sds[tid >> 4];
    float ds1 = sds[16 + (tid >> 4)];
    unsigned sh = (tid & 1) * 16;

    if (v0) {
        float4 o = dec4(cw0 >> sh, ds0);
        long e0 = (long)f0 * 4;
        if (e0 + 4 <= (long)n) {
            __stcs(reinterpret_cast<float4*>(out) + f0, o);
        } else {
            out[e0] = o.x;
            if (e0 + 1 < (long)n) out[e0 + 1] = o.y;
            if (e0 + 2 < (long)n) out[e0 + 2] = o.z;
        }
    }
    if (v1) {
        float4 o = dec4(cw1 >> sh, ds1);
        long e0 = (long)f1 * 4;
        if (e0 + 4 <= (long)n) {
            __stcs(reinterpret_cast<float4*>(out) + f1, o);
        } else {
            out[e0] = o.x;
            if (e0 + 1 < (long)n) out[e0 + 1] = o.y;
            if (e0 + 2 < (long)n) out[e0 + 2] = o.z;
        }
    }
}

extern "C" void kernel_launch(void* const* d_in, const int* in_sizes, int n_in,
                              void* d_out, int out_size) {
    const float* x = (const float*)d_in[0];
    int n = in_sizes[0];
    int nblocks = (n + 63) / 64;
    int grid1 = (nblocks + BLK_PER_CTA - 1) / BLK_PER_CTA;
    int n4 = (n + 3) / 4;
    int grid2 = (n4 + 511) / 512;

    k_pass1<<<grid1, P1_THREADS>>>(x, nblocks, n);
    k_pass2<<<grid2, 256>>>((float*)d_out, nblocks, n);
}

// round 7
// speedup vs baseline: 1.0450x; 1.0450x over previous
#include <cuda_runtime.h>
#include <cstdint>

// ---------------------------------------------------------------------------
// FP4 block quant-dequant, BLOCK=64, scale = 95th pct of |x| per block,
// double-quantized scales (global min/max over blocks).
//
// TWO launches:
//   k_pass1 : 4-chunk TMA (per-warp mbarrier -> TMA/compute overlap);
//             top-5 + premultiplied-threshold quantize; per-CTA
//             atomicMin/Max of scale bits (no fence, no tail)
//   k_pass2 : code LDGs hoisted, per-CTA ds (32 blocks) in smem, arithmetic
//             decode, 2 float4/thread, streaming stores; LAST CTA resets
//             the global min/max bits + counter for the next graph replay
// ---------------------------------------------------------------------------

#define NBLK_CAP 262144   // 16777216 / 64
#define P1_THREADS 128
#define BLK_PER_CTA 128   // one 64-elt block per thread

__device__ float    g_scales[NBLK_CAP];
__device__ unsigned g_codes32[NBLK_CAP * 8];  // 8 u32 per block, element order
__device__ unsigned g_smin_bits = 0x7F800000u;  // reset by pass2's last CTA
__device__ unsigned g_smax_bits = 0u;
__device__ unsigned g_ctr = 0;                  // self-resetting

// ---- minimal mbarrier / bulk-copy PTX helpers ----
__device__ __forceinline__ unsigned smem_u32(const void* p) {
    return (unsigned)__cvta_generic_to_shared(p);
}
__device__ __forceinline__ void mbar_init(unsigned a, unsigned cnt) {
    asm volatile("mbarrier.init.shared.b64 [%0], %1;" :: "r"(a), "r"(cnt) : "memory");
}
__device__ __forceinline__ void mbar_expect_tx(unsigned a, unsigned bytes) {
    asm volatile("mbarrier.arrive.expect_tx.shared.b64 _, [%0], %1;"
                 :: "r"(a), "r"(bytes) : "memory");
}
__device__ __forceinline__ void bulk_g2s(unsigned dst, const void* src,
                                         unsigned bytes, unsigned mbar) {
    asm volatile(
        "cp.async.bulk.shared::cta.global.mbarrier::complete_tx::bytes "
        "[%0], [%1], %2, [%3];"
        :: "r"(dst), "l"(src), "r"(bytes), "r"(mbar) : "memory");
}
__device__ __forceinline__ void mbar_wait(unsigned a, unsigned phase) {
    asm volatile(
        "{\n\t"
        ".reg .pred P;\n\t"
        "WL%=:\n\t"
        "mbarrier.try_wait.parity.acquire.cta.shared::cta.b64 P, [%0], %1;\n\t"
        "@!P bra WL%=;\n\t"
        "}"
        :: "r"(a), "r"(phase) : "memory");
}

// Branchless insert of v (>=0) into descending top-5 (t0 >= ... >= t4).
__device__ __forceinline__ void ins5(float& t0, float& t1, float& t2,
                                     float& t3, float& t4, float v) {
    float a;
    a = fminf(t0, v); t0 = fmaxf(t0, v);
    float b = fminf(t1, a); t1 = fmaxf(t1, a);
    a = fminf(t2, b); t2 = fmaxf(t2, b);
    b = fminf(t3, a); t3 = fmaxf(t3, a);
    t4 = fmaxf(t4, b);
}

// Quantize vs per-block premultiplied midpoints C[5] (uint bits of
// s*{0.375,0.875,1.25,1.75,2.5}); uint compare == float compare for
// positives. Code: bit3 = sign, bits[2:0] = level 0..5.
__device__ __forceinline__ unsigned quant1(float xx, const unsigned* C) {
    unsigned bits = __float_as_uint(xx);
    unsigned mag  = bits & 0x7FFFFFFFu;
    unsigned k = (unsigned)(mag > C[0]) + (unsigned)(mag > C[1])
               + (unsigned)(mag > C[2]) + (unsigned)(mag > C[3])
               + (unsigned)(mag > C[4]);
    return k + ((bits >> 28) & 8u);
}

__global__ void __launch_bounds__(P1_THREADS) k_pass1(const float* __restrict__ x,
                                                      int nblocks, int n) {
    __shared__ __align__(16) float4 sm[BLK_PER_CTA * 16];  // 32 KB
    __shared__ __align__(8) unsigned long long mbar[4];    // one per warp
    __shared__ float shm[4], shx[4];

    int tid = threadIdx.x;
    int wid = tid >> 5;
    long cta_blk0 = (long)blockIdx.x * BLK_PER_CTA;
    long e_base = cta_blk0 * 64;
    bool full = e_base + BLK_PER_CTA * 64 <= (long)n;

    if (full) {
        if (tid < 4) mbar_init(smem_u32(&mbar[tid]), 1);
        __syncthreads();
        if (tid == 0) {
            #pragma unroll
            for (int w = 0; w < 4; w++) {
                unsigned mb = smem_u32(&mbar[w]);
                mbar_expect_tx(mb, 8192);
                bulk_g2s(smem_u32(sm) + w * 8192,
                         x + e_base + (long)w * 2048, 8192, mb);
            }
        }
        // each warp waits only for ITS 8KB chunk -> TMA/compute overlap
        mbar_wait(smem_u32(&mbar[wid]), 0);
    } else {
        #pragma unroll
        for (int k = 0; k < 16; k++) {
            int l4 = tid + k * P1_THREADS;
            long e = e_base + (long)l4 * 4;
            float4 v;
            v.x = (e + 0 < (long)n) ? x[e + 0] : 0.0f;
            v.y = (e + 1 < (long)n) ? x[e + 1] : 0.0f;
            v.z = (e + 2 < (long)n) ? x[e + 2] : 0.0f;
            v.w = (e + 3 < (long)n) ? x[e + 3] : 0.0f;
            sm[l4] = v;
        }
        __syncthreads();
    }

    long b = cta_blk0 + tid;
    bool valid = b < (long)nblocks;
    float vmn = __uint_as_float(0x7F800000u);
    float vmx = 0.0f;

    if (valid) {
        // single smem read of own block, rotated (conflict-free)
        float4 vals[16];
        #pragma unroll
        for (int i = 0; i < 16; i++)
            vals[i] = sm[(tid << 4) | ((i + tid) & 15)];

        // ---- top-5 of |x| ----
        float t0 = 0.f, t1 = 0.f, t2 = 0.f, t3 = 0.f, t4 = 0.f;
        #pragma unroll
        for (int i = 0; i < 16; i++) {
            ins5(t0, t1, t2, t3, t4, fabsf(vals[i].x));
            ins5(t0, t1, t2, t3, t4, fabsf(vals[i].y));
            ins5(t0, t1, t2, t3, t4, fabsf(vals[i].z));
            ins5(t0, t1, t2, t3, t4, fabsf(vals[i].w));
        }

        // 95th pct linear interp: idx = 0.95*63 between sorted[59]=t4,
        // sorted[60]=t3.
        const float idxf = 0.95f * 63.0f;
        const float hw   = idxf - 59.0f;
        const float lw   = 1.0f - hw;
        float s = t4 * lw + t3 * hw;
        s = fmaxf(s, 1e-8f);
        g_scales[b] = s;
        vmn = s; vmx = s;

        unsigned C[5];
        C[0] = __float_as_uint(s * 0.375f);
        C[1] = __float_as_uint(s * 0.875f);
        C[2] = __float_as_uint(s * 1.25f);
        C[3] = __float_as_uint(s * 1.75f);
        C[4] = __float_as_uint(s * 2.5f);

        // ---- quantize + pack (undo rotation when placing nibbles) ----
        unsigned w[8];
        #pragma unroll
        for (int i = 0; i < 8; i++) w[i] = 0u;
        #pragma unroll
        for (int i = 0; i < 16; i++) {
            int j = (i + tid) & 15;   // true float4 position in block
            unsigned nib =  quant1(vals[i].x, C)
                         + (quant1(vals[i].y, C) << 4)
                         + (quant1(vals[i].z, C) << 8)
                         + (quant1(vals[i].w, C) << 12);
            w[j >> 1] += nib << ((j & 1) * 16);
        }
        uint4* c4 = reinterpret_cast<uint4*>(g_codes32);
        c4[(size_t)b * 2 + 0] = make_uint4(w[0], w[1], w[2], w[3]);
        c4[(size_t)b * 2 + 1] = make_uint4(w[4], w[5], w[6], w[7]);
    }

    // ---- CTA min/max reduce -> one atomic pair per CTA ----
    #pragma unroll
    for (int o = 16; o > 0; o >>= 1) {
        vmn = fminf(vmn, __shfl_xor_sync(0xFFFFFFFFu, vmn, o));
        vmx = fmaxf(vmx, __shfl_xor_sync(0xFFFFFFFFu, vmx, o));
    }
    if ((tid & 31) == 0) { shm[wid] = vmn; shx[wid] = vmx; }
    __syncthreads();
    if (tid == 0) {
        float mn = shm[0], mx = shx[0];
        #pragma unroll
        for (int i = 1; i < 4; i++) {
            mn = fminf(mn, shm[i]);
            mx = fmaxf(mx, shx[i]);
        }
        // scales strictly positive -> uint ordering == float ordering
        atomicMin(&g_smin_bits, __float_as_uint(mn));
        atomicMax(&g_smax_bits, __float_as_uint(mx));
    }
}

// Decode 4-bit code: magnitudes {0,0.75,1,1.5,2,3} linear in fp32 bits:
// eb = 0x3F000000 + (k<<22) for k>0; bit3 -> sign.
__device__ __forceinline__ float dec1(unsigned c, float ds) {
    unsigned k  = c & 7u;
    unsigned eb = 0x3F000000u + (k << 22);
    eb = k ? eb : 0u;
    eb |= (c & 8u) << 28;
    return __uint_as_float(eb) * ds;
}

__device__ __forceinline__ float4 dec4(unsigned nib, float ds) {
    float4 o;
    o.x = dec1( nib        & 15u, ds);
    o.y = dec1((nib >>  4) & 15u, ds);
    o.z = dec1((nib >>  8) & 15u, ds);
    o.w = dec1((nib >> 12) & 15u, ds);
    return o;
}

// One CTA covers 512 float4s = 32 quant blocks; ds per block in smem.
__global__ void __launch_bounds__(256) k_pass2(float* __restrict__ out,
                                               int nblocks, int n) {
    __shared__ float sds[32];
    int tid = threadIdx.x;

    int n4 = (n + 3) >> 2;
    int f0 = blockIdx.x * 512 + tid;
    int f1 = f0 + 256;
    bool v0 = f0 < n4, v1 = f1 < n4;

    // hoist code loads so they overlap the ds-prologue's loads
    unsigned cw0 = 0, cw1 = 0;
    if (v0) cw0 = g_codes32[f0 >> 1];
    if (v1) cw1 = g_codes32[f1 >> 1];

    // ds = round((s-smin)/ss)*ss, ss = (smax-smin)/255 (smin dropped in
    // dequant — faithful to reference)
    if (tid < 32) {
        int b = blockIdx.x * 32 + tid;
        float dsv = 0.0f;
        if (b < nblocks) {
            float smin = __uint_as_float(g_smin_bits);
            float smax = __uint_as_float(g_smax_bits);
            bool cond = smax > smin;
            float ss  = cond ? (smax - smin) / 255.0f : 1.0f;
            float iss = 1.0f / ss;
            float s  = g_scales[b];
            float d  = s - smin;
            float q0 = d * iss;
            float q  = fmaf(fmaf(-ss, q0, d), iss, q0);  // == fl(d/ss)
            q = rintf(q);                                // half-to-even
            q = fminf(fmaxf(q, 0.0f), 255.0f);
            if (!cond) q = 0.0f;
            dsv = q * ss;
        }
        sds[tid] = dsv;
    }
    __syncthreads();

    // reset-after-read: once ALL CTAs have passed the sync above (their
    // smin/smax reads are complete), the last CTA resets the global
    // atomics + counter for the next graph replay.
    if (tid == 0) {
        unsigned v = atomicAdd(&g_ctr, 1u);
        if (v == gridDim.x - 1) {
            g_smin_bits = 0x7F800000u;
            g_smax_bits = 0u;
            g_ctr = 0;
        }
    }

    float ds0 = sds[tid >> 4];
    float ds1 = sds[16 + (tid >> 4)];
    unsigned sh = (tid & 1) * 16;

    if (v0) {
        float4 o = dec4(cw0 >> sh, ds0);
        long e0 = (long)f0 * 4;
        if (e0 + 4 <= (long)n) {
            __stcs(reinterpret_cast<float4*>(out) + f0, o);
        } else {
            out[e0] = o.x;
            if (e0 + 1 < (long)n) out[e0 + 1] = o.y;
            if (e0 + 2 < (long)n) out[e0 + 2] = o.z;
        }
    }
    if (v1) {
        float4 o = dec4(cw1 >> sh, ds1);
        long e0 = (long)f1 * 4;
        if (e0 + 4 <= (long)n) {
            __stcs(reinterpret_cast<float4*>(out) + f1, o);
        } else {
            out[e0] = o.x;
            if (e0 + 1 < (long)n) out[e0 + 1] = o.y;
            if (e0 + 2 < (long)n) out[e0 + 2] = o.z;
        }
    }
}

extern "C" void kernel_launch(void* const* d_in, const int* in_sizes, int n_in,
                              void* d_out, int out_size) {
    const float* x = (const float*)d_in[0];
    int n = in_sizes[0];
    int nblocks = (n + 63) / 64;
    int grid1 = (nblocks + BLK_PER_CTA - 1) / BLK_PER_CTA;
    int n4 = (n + 3) / 4;
    int grid2 = (n4 + 511) / 512;

    k_pass1<<<grid1, P1_THREADS>>>(x, nblocks, n);
    k_pass2<<<grid2, 256>>>((float*)d_out, nblocks, n);
}

// round 8
// speedup vs baseline: 1.0942x; 1.0471x over previous
#include <cuda_runtime.h>
#include <cstdint>

// ---------------------------------------------------------------------------
// FP4 block quant-dequant, BLOCK=64, scale = 95th pct of |x| per block,
// double-quantized scales (global min/max over blocks).
//
// TWO launches:
//   k_pass1 : single 32KB TMA bulk load -> smem -> regs (rotated, conflict-
//             free); top-5 + premultiplied-threshold quantize; per-CTA
//             atomicMin/Max of scale bits        [R4 config — best measured]
//   k_pass2 : 4 float4/thread, per-CTA ds (64 blocks) in smem, arithmetic
//             decode, streaming stores; LAST CTA resets min/max + counter
// ---------------------------------------------------------------------------

#define NBLK_CAP 262144   // 16777216 / 64
#define P1_THREADS 128
#define BLK_PER_CTA 128   // one 64-elt block per thread
#define P2_F4_PER_CTA 1024

__device__ float    g_scales[NBLK_CAP];
__device__ unsigned g_codes32[NBLK_CAP * 8];  // 8 u32 per block, element order
__device__ unsigned g_smin_bits = 0x7F800000u;  // reset by pass2's last CTA
__device__ unsigned g_smax_bits = 0u;
__device__ unsigned g_ctr = 0;                  // self-resetting

// ---- minimal mbarrier / bulk-copy PTX helpers ----
__device__ __forceinline__ unsigned smem_u32(const void* p) {
    return (unsigned)__cvta_generic_to_shared(p);
}
__device__ __forceinline__ void mbar_init(unsigned a, unsigned cnt) {
    asm volatile("mbarrier.init.shared.b64 [%0], %1;" :: "r"(a), "r"(cnt) : "memory");
}
__device__ __forceinline__ void mbar_expect_tx(unsigned a, unsigned bytes) {
    asm volatile("mbarrier.arrive.expect_tx.shared.b64 _, [%0], %1;"
                 :: "r"(a), "r"(bytes) : "memory");
}
__device__ __forceinline__ void bulk_g2s(unsigned dst, const void* src,
                                         unsigned bytes, unsigned mbar) {
    asm volatile(
        "cp.async.bulk.shared::cta.global.mbarrier::complete_tx::bytes "
        "[%0], [%1], %2, [%3];"
        :: "r"(dst), "l"(src), "r"(bytes), "r"(mbar) : "memory");
}
__device__ __forceinline__ void mbar_wait(unsigned a, unsigned phase) {
    asm volatile(
        "{\n\t"
        ".reg .pred P;\n\t"
        "WL%=:\n\t"
        "mbarrier.try_wait.parity.acquire.cta.shared::cta.b64 P, [%0], %1;\n\t"
        "@!P bra WL%=;\n\t"
        "}"
        :: "r"(a), "r"(phase) : "memory");
}

// Branchless insert of v (>=0) into descending top-5 (t0 >= ... >= t4).
__device__ __forceinline__ void ins5(float& t0, float& t1, float& t2,
                                     float& t3, float& t4, float v) {
    float a;
    a = fminf(t0, v); t0 = fmaxf(t0, v);
    float b = fminf(t1, a); t1 = fmaxf(t1, a);
    a = fminf(t2, b); t2 = fmaxf(t2, b);
    b = fminf(t3, a); t3 = fmaxf(t3, a);
    t4 = fmaxf(t4, b);
}

// Quantize vs per-block premultiplied midpoints C[5] (uint bits of
// s*{0.375,0.875,1.25,1.75,2.5}); uint compare == float compare for
// positives. Code: bit3 = sign, bits[2:0] = level 0..5.
__device__ __forceinline__ unsigned quant1(float xx, const unsigned* C) {
    unsigned bits = __float_as_uint(xx);
    unsigned mag  = bits & 0x7FFFFFFFu;
    unsigned k = (unsigned)(mag > C[0]) + (unsigned)(mag > C[1])
               + (unsigned)(mag > C[2]) + (unsigned)(mag > C[3])
               + (unsigned)(mag > C[4]);
    return k + ((bits >> 28) & 8u);
}

__global__ void __launch_bounds__(P1_THREADS) k_pass1(const float* __restrict__ x,
                                                      int nblocks, int n) {
    __shared__ __align__(16) float4 sm[BLK_PER_CTA * 16];  // 32 KB
    __shared__ __align__(8) unsigned long long mbar;
    __shared__ float shm[4], shx[4];

    int tid = threadIdx.x;
    long cta_blk0 = (long)blockIdx.x * BLK_PER_CTA;
    long e_base = cta_blk0 * 64;
    bool full = e_base + BLK_PER_CTA * 64 <= (long)n;

    if (full) {
        if (tid == 0) mbar_init(smem_u32(&mbar), 1);
        __syncthreads();
        if (tid == 0) {
            unsigned mb = smem_u32(&mbar);
            mbar_expect_tx(mb, BLK_PER_CTA * 256);
            bulk_g2s(smem_u32(sm), x + e_base, BLK_PER_CTA * 256, mb);
        }
        mbar_wait(smem_u32(&mbar), 0);
    } else {
        #pragma unroll
        for (int k = 0; k < 16; k++) {
            int l4 = tid + k * P1_THREADS;
            long e = e_base + (long)l4 * 4;
            float4 v;
            v.x = (e + 0 < (long)n) ? x[e + 0] : 0.0f;
            v.y = (e + 1 < (long)n) ? x[e + 1] : 0.0f;
            v.z = (e + 2 < (long)n) ? x[e + 2] : 0.0f;
            v.w = (e + 3 < (long)n) ? x[e + 3] : 0.0f;
            sm[l4] = v;
        }
        __syncthreads();
    }

    long b = cta_blk0 + tid;
    bool valid = b < (long)nblocks;
    float vmn = __uint_as_float(0x7F800000u);
    float vmx = 0.0f;

    if (valid) {
        // single smem read of own block, rotated (conflict-free)
        float4 vals[16];
        #pragma unroll
        for (int i = 0; i < 16; i++)
            vals[i] = sm[(tid << 4) | ((i + tid) & 15)];

        // ---- top-5 of |x| ----
        float t0 = 0.f, t1 = 0.f, t2 = 0.f, t3 = 0.f, t4 = 0.f;
        #pragma unroll
        for (int i = 0; i < 16; i++) {
            ins5(t0, t1, t2, t3, t4, fabsf(vals[i].x));
            ins5(t0, t1, t2, t3, t4, fabsf(vals[i].y));
            ins5(t0, t1, t2, t3, t4, fabsf(vals[i].z));
            ins5(t0, t1, t2, t3, t4, fabsf(vals[i].w));
        }

        // 95th pct linear interp: idx = 0.95*63 between sorted[59]=t4,
        // sorted[60]=t3.
        const float idxf = 0.95f * 63.0f;
        const float hw   = idxf - 59.0f;
        const float lw   = 1.0f - hw;
        float s = t4 * lw + t3 * hw;
        s = fmaxf(s, 1e-8f);
        g_scales[b] = s;
        vmn = s; vmx = s;

        unsigned C[5];
        C[0] = __float_as_uint(s * 0.375f);
        C[1] = __float_as_uint(s * 0.875f);
        C[2] = __float_as_uint(s * 1.25f);
        C[3] = __float_as_uint(s * 1.75f);
        C[4] = __float_as_uint(s * 2.5f);

        // ---- quantize + pack (undo rotation when placing nibbles) ----
        unsigned w[8];
        #pragma unroll
        for (int i = 0; i < 8; i++) w[i] = 0u;
        #pragma unroll
        for (int i = 0; i < 16; i++) {
            int j = (i + tid) & 15;   // true float4 position in block
            unsigned nib =  quant1(vals[i].x, C)
                         | (quant1(vals[i].y, C) << 4)
                         | (quant1(vals[i].z, C) << 8)
                         | (quant1(vals[i].w, C) << 12);
            w[j >> 1] |= nib << ((j & 1) * 16);
        }
        uint4* c4 = reinterpret_cast<uint4*>(g_codes32);
        c4[(size_t)b * 2 + 0] = make_uint4(w[0], w[1], w[2], w[3]);
        c4[(size_t)b * 2 + 1] = make_uint4(w[4], w[5], w[6], w[7]);
    }

    // ---- CTA min/max reduce -> one atomic pair per CTA ----
    #pragma unroll
    for (int o = 16; o > 0; o >>= 1) {
        vmn = fminf(vmn, __shfl_xor_sync(0xFFFFFFFFu, vmn, o));
        vmx = fmaxf(vmx, __shfl_xor_sync(0xFFFFFFFFu, vmx, o));
    }
    int wid = tid >> 5;
    if ((tid & 31) == 0) { shm[wid] = vmn; shx[wid] = vmx; }
    __syncthreads();
    if (tid == 0) {
        float mn = shm[0], mx = shx[0];
        #pragma unroll
        for (int i = 1; i < 4; i++) {
            mn = fminf(mn, shm[i]);
            mx = fmaxf(mx, shx[i]);
        }
        // scales strictly positive -> uint ordering == float ordering
        atomicMin(&g_smin_bits, __float_as_uint(mn));
        atomicMax(&g_smax_bits, __float_as_uint(mx));
    }
}

// Decode 4-bit code: magnitudes {0,0.75,1,1.5,2,3} linear in fp32 bits:
// eb = 0x3F000000 + (k<<22) for k>0; bit3 -> sign.
__device__ __forceinline__ float dec1(unsigned c, float ds) {
    unsigned k  = c & 7u;
    unsigned eb = 0x3F000000u + (k << 22);
    eb = k ? eb : 0u;
    eb |= (c & 8u) << 28;
    return __uint_as_float(eb) * ds;
}

__device__ __forceinline__ float4 dec4(unsigned nib, float ds) {
    float4 o;
    o.x = dec1( nib        & 15u, ds);
    o.y = dec1((nib >>  4) & 15u, ds);
    o.z = dec1((nib >>  8) & 15u, ds);
    o.w = dec1((nib >> 12) & 15u, ds);
    return o;
}

// One CTA covers 1024 float4s = 64 quant blocks; ds per block in smem.
__global__ void __launch_bounds__(256) k_pass2(float* __restrict__ out,
                                               int nblocks, int n) {
    __shared__ float sds[64];
    int tid = threadIdx.x;
    int n4 = (n + 3) >> 2;
    int fbase = blockIdx.x * P2_F4_PER_CTA + tid;

    // hoist all code loads (4 independent LDGs)
    int f[4];
    unsigned cw[4];
    bool v[4];
    #pragma unroll
    for (int j = 0; j < 4; j++) {
        f[j] = fbase + j * 256;
        v[j] = f[j] < n4;
        cw[j] = v[j] ? g_codes32[f[j] >> 1] : 0u;
    }

    // ds = round((s-smin)/ss)*ss, ss = (smax-smin)/255 (smin dropped in
    // dequant — faithful to reference)
    if (tid < 64) {
        int b = blockIdx.x * 64 + tid;
        float dsv = 0.0f;
        if (b < nblocks) {
            float smin = __uint_as_float(g_smin_bits);
            float smax = __uint_as_float(g_smax_bits);
            bool cond = smax > smin;
            float ss  = cond ? (smax - smin) / 255.0f : 1.0f;
            float iss = 1.0f / ss;
            float s  = g_scales[b];
            float d  = s - smin;
            float q0 = d * iss;
            float q  = fmaf(fmaf(-ss, q0, d), iss, q0);  // == fl(d/ss)
            q = rintf(q);                                // half-to-even
            q = fminf(fmaxf(q, 0.0f), 255.0f);
            if (!cond) q = 0.0f;
            dsv = q * ss;
        }
        sds[tid] = dsv;
    }
    __syncthreads();

    // reset-after-read: once all CTAs passed the sync (min/max reads done),
    // the last CTA resets the global atomics + counter for the next replay.
    if (tid == 0) {
        unsigned c = atomicAdd(&g_ctr, 1u);
        if (c == gridDim.x - 1) {
            g_smin_bits = 0x7F800000u;
            g_smax_bits = 0u;
            g_ctr = 0;
        }
    }

    unsigned sh = (tid & 1) * 16;
    #pragma unroll
    for (int j = 0; j < 4; j++) {
        if (!v[j]) continue;
        float ds = sds[(tid >> 4) + j * 16];
        float4 o = dec4(cw[j] >> sh, ds);
        long e0 = (long)f[j] * 4;
        if (e0 + 4 <= (long)n) {
            __stcs(reinterpret_cast<float4*>(out) + f[j], o);
        } else {
            out[e0] = o.x;
            if (e0 + 1 < (long)n) out[e0 + 1] = o.y;
            if (e0 + 2 < (long)n) out[e0 + 2] = o.z;
        }
    }
}

extern "C" void kernel_launch(void* const* d_in, const int* in_sizes, int n_in,
                              void* d_out, int out_size) {
    const float* x = (const float*)d_in[0];
    int n = in_sizes[0];
    int nblocks = (n + 63) / 64;
    int grid1 = (nblocks + BLK_PER_CTA - 1) / BLK_PER_CTA;
    int n4 = (n + 3) / 4;
    int grid2 = (n4 + P2_F4_PER_CTA - 1) / P2_F4_PER_CTA;

    k_pass1<<<grid1, P1_THREADS>>>(x, nblocks, n);
    k_pass2<<<grid2, 256>>>((float*)d_out, nblocks, n);
}